// round 6
// baseline (speedup 1.0000x reference)
#include <cuda_runtime.h>

// CustomRouterRouter — reference-rounding-matched implementation.
//
// out[l,e] = rr_e(hs) + rr2(hs) * lin[l,e],  lin = (x@W.T + b) / rowsum
// rowsum can be ~5e-4, amplifying dot rounding ~2000x -> must REPRODUCE the
// reference's rounding realization.
// This round: Eigen/NEON gemv realization (jax CPU on Grace): 4 SIMD-lane
// accumulators (lane j takes k ≡ j mod 4), fused FMA per lane, ascending k,
// horizontal reduction in Eigen predux order: (a0+a2)+(a1+a3).

#define FT 0.5f

__global__ __launch_bounds__(64) void router_seq_kernel(
    const float4* __restrict__ x4,
    const float*  __restrict__ weights,
    const float4* __restrict__ W4,
    const float*  __restrict__ b,
    float*        __restrict__ out,
    int L, int Hv)
{
    const int t   = blockIdx.x * blockDim.x + threadIdx.x;
    const int row = t >> 1;
    const int e   = t & 1;
    if (row >= L) return;

    const float4* __restrict__ xr = x4 + (size_t)row * Hv;
    const float4* __restrict__ wr = W4 + (size_t)e * Hv;

    // 4 independent lane accumulators (SIMD lanes), ascending over packets.
    float a0 = 0.f, a1 = 0.f, a2 = 0.f, a3 = 0.f;
    #pragma unroll 8
    for (int i = 0; i < Hv; i++) {
        const float4 xv = xr[i];
        const float4 wv = __ldg(&wr[i]);
        a0 = fmaf(xv.x, wv.x, a0);
        a1 = fmaf(xv.y, wv.y, a1);
        a2 = fmaf(xv.z, wv.z, a2);
        a3 = fmaf(xv.w, wv.w, a3);
    }
    // Eigen NEON predux order: vadd(low, high) = (a0+a2, a1+a3), then vpadd.
    const float acc = __fadd_rn(__fadd_rn(a0, a2), __fadd_rn(a1, a3));

    // lin_e = dot_e + b_e   (single rounding)
    const float lin = __fadd_rn(acc, __ldg(&b[e]));

    // den = lin0 + lin1 (single rounding). Partner thread is adjacent lane.
    const float other = __shfl_xor_sync(0xffffffffu, lin, 1);
    const float lin0  = (e == 0) ? lin : other;
    const float lin1  = (e == 0) ? other : lin;
    const float den   = __fadd_rn(lin0, lin1);

    // IEEE correctly-rounded fp32 division.
    const float l = __fdiv_rn(lin, den);

    // hs = weights[row // (L/2)][0]; weights is (2,2) row-major.
    const float hs = __ldg(&weights[(row >= (L >> 1)) ? 2 : 0]);

    float rr_self, rr2;
    if (hs >= FT) {
        rr2     = __fdiv_rn(__fsub_rn(1.0f, hs), 1.0f - FT);
        rr_self = (e == 0) ? __fdiv_rn(__fsub_rn(hs, FT), 1.0f - FT) : 0.0f;
    } else {
        rr2     = __fdiv_rn(hs, FT);
        rr_self = (e == 0) ? 0.0f : __fdiv_rn(__fsub_rn(FT, hs), FT);
    }

    // einsum epilogue: out = rr_self + round(rr2 * lin), mul then add.
    out[row * 2 + e] = __fadd_rn(rr_self, __fmul_rn(rr2, l));
}

extern "C" void kernel_launch(void* const* d_in, const int* in_sizes, int n_in,
                              void* d_out, int out_size) {
    const float* x       = (const float*)d_in[0];
    const float* weights = (const float*)d_in[1];
    const float* W       = (const float*)d_in[2];
    const float* b       = (const float*)d_in[3];
    float* out = (float*)d_out;

    const int E  = in_sizes[3];            // 2
    const int H  = in_sizes[2] / E;        // 4096
    const int L  = in_sizes[0] / H;        // 8192
    const int Hv = H / 4;                  // 1024

    const int total   = L * 2;             // one thread per (row, e)
    const int threads = 64;
    const int blocks  = (total + threads - 1) / threads;

    router_seq_kernel<<<blocks, threads>>>((const float4*)x, weights,
                                           (const float4*)W, b, out, L, Hv);
}

// round 7
// speedup vs baseline: 2.5083x; 2.5083x over previous
#include <cuda_runtime.h>

// CustomRouterRouter — reference-rounding-matched (Eigen/NEON gemv realization)
// + deep register prefetch for DRAM-latency hiding.
//
// Numerics (LOCKED, passed R6 @ rel_err 3.06e-5): per (row,e), 4 SIMD-lane fp32
// accumulators with fused FMA, lane j takes k ≡ j (mod 4), ascending packets;
// horizontal reduce in Eigen predux order (a0+a2)+(a1+a3); single-rounding
// epilogue (+b, den add, IEEE divide, mul-then-add).
//
// Perf: total parallelism is fixed at 16384 threads (one per output element),
// so DRAM latency must be covered by per-thread MLP. Rotating 16-deep float4
// register buffers keep ~32 LDG.128 in flight per thread.

#define FT 0.5f
#define PFD 16   // prefetch depth in float4 packets

__global__ __launch_bounds__(64) void router_seq_kernel(
    const float4* __restrict__ x4,
    const float*  __restrict__ weights,
    const float4* __restrict__ W4,
    const float*  __restrict__ b,
    float*        __restrict__ out,
    int L, int Hv)
{
    const int t   = blockIdx.x * blockDim.x + threadIdx.x;
    const int row = t >> 1;
    const int e   = t & 1;
    if (row >= L) return;

    const float4* __restrict__ xr = x4 + (size_t)row * Hv;
    const float4* __restrict__ wr = W4 + (size_t)e * Hv;

    // 4 independent lane accumulators (NEON lanes), ascending packet order.
    float a0 = 0.f, a1 = 0.f, a2 = 0.f, a3 = 0.f;

    // Prime the prefetch buffers with packets [0, PFD).
    float4 xb[PFD], wb[PFD];
    #pragma unroll
    for (int j = 0; j < PFD; j++) {
        xb[j] = xr[j];
        wb[j] = __ldg(&wr[j]);
    }

    // Main loop: consume [i, i+PFD), prefetch [i+PFD, i+2*PFD).
    // Requires Hv % PFD == 0 and Hv >= 2*PFD (Hv = 1024, PFD = 16).
    #pragma unroll 1
    for (int i = 0; i < Hv - PFD; i += PFD) {
        #pragma unroll
        for (int j = 0; j < PFD; j++) {
            const float4 xv = xb[j];
            const float4 wv = wb[j];
            xb[j] = xr[i + PFD + j];
            wb[j] = __ldg(&wr[i + PFD + j]);
            a0 = fmaf(xv.x, wv.x, a0);
            a1 = fmaf(xv.y, wv.y, a1);
            a2 = fmaf(xv.z, wv.z, a2);
            a3 = fmaf(xv.w, wv.w, a3);
        }
    }
    // Tail: consume the last PFD packets.
    #pragma unroll
    for (int j = 0; j < PFD; j++) {
        const float4 xv = xb[j];
        const float4 wv = wb[j];
        a0 = fmaf(xv.x, wv.x, a0);
        a1 = fmaf(xv.y, wv.y, a1);
        a2 = fmaf(xv.z, wv.z, a2);
        a3 = fmaf(xv.w, wv.w, a3);
    }

    // Eigen NEON predux order: (a0+a2) + (a1+a3).
    const float acc = __fadd_rn(__fadd_rn(a0, a2), __fadd_rn(a1, a3));

    // lin_e = dot_e + b_e   (single rounding)
    const float lin = __fadd_rn(acc, __ldg(&b[e]));

    // den = lin0 + lin1 (single rounding). Partner thread is adjacent lane.
    const float other = __shfl_xor_sync(0xffffffffu, lin, 1);
    const float lin0  = (e == 0) ? lin : other;
    const float lin1  = (e == 0) ? other : lin;
    const float den   = __fadd_rn(lin0, lin1);

    // IEEE correctly-rounded fp32 division.
    const float l = __fdiv_rn(lin, den);

    // hs = weights[row // (L/2)][0]; weights is (2,2) row-major.
    const float hs = __ldg(&weights[(row >= (L >> 1)) ? 2 : 0]);

    float rr_self, rr2;
    if (hs >= FT) {
        rr2     = __fdiv_rn(__fsub_rn(1.0f, hs), 1.0f - FT);
        rr_self = (e == 0) ? __fdiv_rn(__fsub_rn(hs, FT), 1.0f - FT) : 0.0f;
    } else {
        rr2     = __fdiv_rn(hs, FT);
        rr_self = (e == 0) ? 0.0f : __fdiv_rn(__fsub_rn(FT, hs), FT);
    }

    // einsum epilogue: out = rr_self + round(rr2 * lin), mul then add.
    out[row * 2 + e] = __fadd_rn(rr_self, __fmul_rn(rr2, l));
}

extern "C" void kernel_launch(void* const* d_in, const int* in_sizes, int n_in,
                              void* d_out, int out_size) {
    const float* x       = (const float*)d_in[0];
    const float* weights = (const float*)d_in[1];
    const float* W       = (const float*)d_in[2];
    const float* b       = (const float*)d_in[3];
    float* out = (float*)d_out;

    const int E  = in_sizes[3];            // 2
    const int H  = in_sizes[2] / E;        // 4096
    const int L  = in_sizes[0] / H;        // 8192
    const int Hv = H / 4;                  // 1024

    const int total   = L * 2;             // one thread per (row, e)
    const int threads = 64;
    const int blocks  = (total + threads - 1) / threads;

    router_seq_kernel<<<blocks, threads>>>((const float4*)x, weights,
                                           (const float4*)W, b, out, L, Hv);
}